// round 8
// baseline (speedup 1.0000x reference)
#include <cuda_runtime.h>
#include <math_constants.h>

// Chamfer distance: B=8, N=M=4096, D=2 on sm_100a — exact NN, warp-uniform.
// K1: bin-sort each of 16 arrays into 256 x-bins (histogram+scan+scatter).
// K2: per query (one thread, iterated in sorted order):
//   Phase A: scan fixed 48-pt rank-window around own index -> upper bound r.
//   Phase B: candidate range = bins covering [qx-r, qx+r] (contiguous);
//            warp-union of ranges -> ONE uniform broadcast-LDS scan, 4 accums.
//   Exact min; sqrt; block reduce; atomicAdd.

#define NPTS    4096
#define THREADS 256
#define NBINS   256
#define NARR    16
#define RANGE_LO (-6.0f)
#define RANGE_W  (12.0f / NBINS)
#define INV_W    (NBINS / 12.0f)
#define QCHUNKS (NPTS / THREADS)   // 16

__device__ float2 g_sorted[NARR][NPTS];     // 512 KB
__device__ int    g_start[NARR][NBINS + 1];

// ---------------- K1: bin + scatter (16 blocks) ----------------
__global__ __launch_bounds__(THREADS)
void bin_kernel(const float* __restrict__ x, const float* __restrict__ tgt)
{
    __shared__ int s_cnt[NBINS];
    __shared__ int s_start[NBINS + 1];

    const int a    = blockIdx.x;
    const int side = a & 1;
    const int b    = a >> 1;
    const float2* src = (const float2*)((side ? tgt : x) + (size_t)b * NPTS * 2);

    s_cnt[threadIdx.x] = 0;
    __syncthreads();

    float2 pts[NPTS / THREADS];
    int    bins[NPTS / THREADS];
    #pragma unroll
    for (int k = 0; k < NPTS / THREADS; k++) {
        float2 p = src[k * THREADS + threadIdx.x];
        int bi = (int)floorf((p.x - RANGE_LO) * INV_W);
        bi = max(0, min(NBINS - 1, bi));
        pts[k] = p;
        bins[k] = bi;
        atomicAdd(&s_cnt[bi], 1);
    }
    __syncthreads();

    if (threadIdx.x < 32) {
        int lane = threadIdx.x;
        int v[8], tot = 0;
        #pragma unroll
        for (int j = 0; j < 8; j++) { v[j] = s_cnt[lane * 8 + j]; tot += v[j]; }
        int sum = tot;
        #pragma unroll
        for (int off = 1; off < 32; off <<= 1) {
            int n = __shfl_up_sync(0xFFFFFFFFu, sum, off);
            if (lane >= off) sum += n;
        }
        int excl = sum - tot;
        #pragma unroll
        for (int j = 0; j < 8; j++) { s_start[lane * 8 + j] = excl; excl += v[j]; }
        if (lane == 31) s_start[NBINS] = NPTS;
    }
    __syncthreads();

    g_start[a][threadIdx.x] = s_start[threadIdx.x];
    if (threadIdx.x == 0) g_start[a][NBINS] = NPTS;

    s_cnt[threadIdx.x] = s_start[threadIdx.x];
    __syncthreads();

    #pragma unroll
    for (int k = 0; k < NPTS / THREADS; k++) {
        int off = atomicAdd(&s_cnt[bins[k]], 1);
        g_sorted[a][off] = pts[k];
    }
}

// ---------------- K2: query (256 blocks) ----------------
__global__ __launch_bounds__(THREADS)
void query_kernel(float* __restrict__ out)
{
    extern __shared__ __align__(16) float4 s_uvh[];   // NPTS * 16B = 64 KB
    __shared__ int   s_s[NBINS + 1];
    __shared__ float s_warp[THREADS / 32];

    const int chunk = blockIdx.x & (QCHUNKS - 1);
    const int pair  = blockIdx.x >> 4;
    const int dir   = pair & 1;
    const int b     = pair >> 1;
    const int qa    = b * 2 + dir;
    const int da    = b * 2 + (dir ^ 1);

    // Stage DB in (u0,u1,h) form: s = h + qx*u0 + qy*u1 = |t-q|^2 - |q|^2.
    {
        const float2* src = g_sorted[da];
        #pragma unroll
        for (int k = 0; k < NPTS / THREADS; k++) {
            int p = k * THREADS + threadIdx.x;
            float2 t = src[p];
            s_uvh[p] = make_float4(-2.0f * t.x, -2.0f * t.y,
                                   fmaf(t.x, t.x, t.y * t.y), 0.0f);
        }
        for (int i = threadIdx.x; i < NBINS + 1; i += THREADS)
            s_s[i] = g_start[da][i];
    }
    __syncthreads();

    const int qi = chunk * THREADS + threadIdx.x;
    const float2 q = g_sorted[qa][qi];       // sorted order -> coherent warps
    const float q2 = fmaf(q.x, q.x, q.y * q.y);

    float ms0 = CUDART_INF_F, ms1 = CUDART_INF_F;
    float ms2 = CUDART_INF_F, ms3 = CUDART_INF_F;

    // ---- Phase A: fixed 48-pt rank window -> upper bound ----
    {
        int lo = min(max(qi - 24, 0), NPTS - 48);
        #pragma unroll
        for (int j = 0; j < 48; j += 4) {
            float4 t0 = s_uvh[lo + j + 0];
            float4 t1 = s_uvh[lo + j + 1];
            float4 t2 = s_uvh[lo + j + 2];
            float4 t3 = s_uvh[lo + j + 3];
            ms0 = fminf(ms0, fmaf(q.x, t0.x, fmaf(q.y, t0.y, t0.z)));
            ms1 = fminf(ms1, fmaf(q.x, t1.x, fmaf(q.y, t1.y, t1.z)));
            ms2 = fminf(ms2, fmaf(q.x, t2.x, fmaf(q.y, t2.y, t2.z)));
            ms3 = fminf(ms3, fmaf(q.x, t3.x, fmaf(q.y, t3.y, t3.z)));
        }
    }
    float bA = fminf(fminf(ms0, ms1), fminf(ms2, ms3));
    float r  = sqrtf(fmaxf(bA + q2, 0.0f)) * 1.001f + 1e-5f;

    // ---- Phase B: warp-uniform exact scan over bin-covered range ----
    int lob = max((int)floorf((q.x - r - RANGE_LO) * INV_W), 0);
    int hib = min((int)floorf((q.x + r - RANGE_LO) * INV_W), NBINS - 1);
    int li  = s_s[lob];
    int hi  = s_s[hib + 1];
    int wlo = __reduce_min_sync(0xFFFFFFFFu, li);
    int whi = __reduce_max_sync(0xFFFFFFFFu, hi);

    int j = wlo;
    for (; j + 4 <= whi; j += 4) {
        float4 t0 = s_uvh[j + 0];
        float4 t1 = s_uvh[j + 1];
        float4 t2 = s_uvh[j + 2];
        float4 t3 = s_uvh[j + 3];
        ms0 = fminf(ms0, fmaf(q.x, t0.x, fmaf(q.y, t0.y, t0.z)));
        ms1 = fminf(ms1, fmaf(q.x, t1.x, fmaf(q.y, t1.y, t1.z)));
        ms2 = fminf(ms2, fmaf(q.x, t2.x, fmaf(q.y, t2.y, t2.z)));
        ms3 = fminf(ms3, fmaf(q.x, t3.x, fmaf(q.y, t3.y, t3.z)));
    }
    for (; j < whi; j++) {
        float4 t0 = s_uvh[j];
        ms0 = fminf(ms0, fmaf(q.x, t0.x, fmaf(q.y, t0.y, t0.z)));
    }

    float best = fmaxf(fminf(fminf(ms0, ms1), fminf(ms2, ms3)) + q2, 0.0f);
    float v = sqrtf(best);

    // ---- reduce + atomic ----
    #pragma unroll
    for (int off = 16; off > 0; off >>= 1)
        v += __shfl_down_sync(0xFFFFFFFFu, v, off);
    const int lane = threadIdx.x & 31;
    const int wid  = threadIdx.x >> 5;
    if (lane == 0) s_warp[wid] = v;
    __syncthreads();
    if (wid == 0) {
        float w = (lane < THREADS / 32) ? s_warp[lane] : 0.0f;
        #pragma unroll
        for (int off = 4; off > 0; off >>= 1)
            w += __shfl_down_sync(0xFFFFFFFFu, w, off);
        if (lane == 0)
            atomicAdd(out, w * (1.0f / 32768.0f));
    }
}

extern "C" void kernel_launch(void* const* d_in, const int* in_sizes, int n_in,
                              void* d_out, int out_size)
{
    const float* x   = (const float*)d_in[0];   // [8,4096,2] f32
    const float* tgt = (const float*)d_in[1];   // [8,4096,2] f32
    float* out = (float*)d_out;

    (void)in_sizes; (void)n_in; (void)out_size;

    static const size_t SMEM = NPTS * sizeof(float4);   // 64 KB
    cudaFuncSetAttribute(query_kernel,
                         cudaFuncAttributeMaxDynamicSharedMemorySize, (int)SMEM);

    cudaMemsetAsync(d_out, 0, sizeof(float));
    bin_kernel<<<NARR, THREADS>>>(x, tgt);
    query_kernel<<<NARR * QCHUNKS, THREADS, SMEM>>>(out);
}